// round 5
// baseline (speedup 1.0000x reference)
#include <cuda_runtime.h>
#include <cstdint>

#define B_  2
#define N_  4
#define D_  48
#define H_  28
#define W_  60
#define C_  64
#define NX_ 192
#define NY_ 192
// NZ = 1

// Scratch accumulator in C-contiguous layout (B, NY, NX, C) so vector reds work.
__device__ float g_scratch[B_ * NY_ * NX_ * C_];
// Per-(b,n): 9 floats of combine = R @ inv(K), then 3 floats of trans.
__device__ float g_geo[B_ * N_ * 12];

// ---------------------------------------------------------------------------
// Setup: 8 (b,n) pairs -> combine rows + trans. Mimics float32 reference math.
// ---------------------------------------------------------------------------
__global__ void setup_kernel(const float* __restrict__ intr,
                             const float* __restrict__ pose) {
    int i = threadIdx.x;
    if (i >= B_ * N_) return;
    const float* K = intr + i * 9;
    const float* P = pose + i * 16;

    float a = K[0], bb = K[1], c = K[2];
    float d = K[3], e  = K[4], f = K[5];
    float g = K[6], h  = K[7], ii = K[8];

    float A0 = e * ii - f * h;
    float A1 = f * g  - d * ii;
    float A2 = d * h  - e * g;
    float det = a * A0 + bb * A1 + c * A2;

    float inv[9];
    inv[0] = A0 / det;             inv[1] = (c * h - bb * ii) / det; inv[2] = (bb * f - c * e) / det;
    inv[3] = A1 / det;             inv[4] = (a * ii - c * g) / det;  inv[5] = (c * d - a * f) / det;
    inv[6] = A2 / det;             inv[7] = (bb * g - a * h) / det;  inv[8] = (a * e - bb * d) / det;

    for (int r = 0; r < 3; r++) {
        for (int j = 0; j < 3; j++) {
            float s = P[r * 4 + 0] * inv[0 * 3 + j];
            s = fmaf(P[r * 4 + 1], inv[1 * 3 + j], s);
            s = fmaf(P[r * 4 + 2], inv[2 * 3 + j], s);
            g_geo[i * 12 + r * 3 + j] = s;
        }
        g_geo[i * 12 + 9 + r] = P[r * 4 + 3];
    }
}

// ---------------------------------------------------------------------------
// Zero the scratch each launch (deterministic, graph-capturable).
// ---------------------------------------------------------------------------
__global__ void zero_kernel() {
    const int n4 = (B_ * NY_ * NX_ * C_) / 4;
    float4* p = (float4*)g_scratch;
    for (int idx = blockIdx.x * blockDim.x + threadIdx.x; idx < n4;
         idx += gridDim.x * blockDim.x)
        p[idx] = make_float4(0.f, 0.f, 0.f, 0.f);
}

// Vectorized fire-and-forget reduction (sm_90+): one 16B red per sub-lane.
__device__ __forceinline__ void red_add_v4(float* addr, float4 v) {
    asm volatile("red.global.add.v4.f32 [%0], {%1, %2, %3, %4};"
                 :: "l"(addr), "f"(v.x), "f"(v.y), "f"(v.z), "f"(v.w)
                 : "memory");
}

// ---------------------------------------------------------------------------
// Scatter: one HALF-warp (16 lanes) per (b,d,h,w) group; sub-lane owns 4
// channels (float4 loads, v4 reds). Merges the N=4 views in registers when
// they hit the same voxel (data-driven check, nothing baked in).
// Non-kept points (incl. all out-of-frustum d) skip their x loads entirely.
// ---------------------------------------------------------------------------
__global__ void __launch_bounds__(256)
scatter_kernel(const float* __restrict__ x) {
    int tid   = blockIdx.x * blockDim.x + threadIdx.x;
    int group = tid >> 4;                       // one group per 16 lanes
    int sub   = threadIdx.x & 15;               // channel sub-lane
    const int NG = B_ * D_ * H_ * W_;
    if (group >= NG) return;

    int w = group % W_;
    int t = group / W_;
    int h = t % H_;  t /= H_;
    int d = t % D_;
    int b = t / D_;

    float df = 2.0f + (float)d;                 // ds = arange(2,50,1)
    float u  = (float)w * (479.0f / 59.0f);     // linspace(0, 479, 60)
    float v  = (float)h * (223.0f / 27.0f);     // linspace(0, 223, 28)
    float p0 = u * df, p1 = v * df, p2 = df;

    const float* xb = x
        + ((((size_t)b * N_ + 0) * D_ + d) * H_ + h) * (size_t)(W_ * C_)
        + (size_t)w * C_ + sub * 4;

    int    cur = -1;
    float4 acc = make_float4(0.f, 0.f, 0.f, 0.f);

    #pragma unroll
    for (int n = 0; n < N_; n++) {
        const float* G = g_geo + (b * N_ + n) * 12;
        float dx = G[0] * p0; dx = fmaf(G[1], p1, dx); dx = fmaf(G[2], p2, dx);
        float dy = G[3] * p0; dy = fmaf(G[4], p1, dy); dy = fmaf(G[5], p2, dy);
        float dz = G[6] * p0; dz = fmaf(G[7], p1, dz); dz = fmaf(G[8], p2, dz);
        float gxf = dx + G[9];
        float gyf = dy + G[10];
        float gzf = dz + G[11];

        // Truncation toward zero == jnp astype(int32); (-0.5 -> 0 is KEPT in both)
        int gx = (int)(gxf * 4.0f + 96.0f);
        int gy = (int)(gyf * 4.0f + 96.0f);
        int gz = (int)__fdiv_rn(gzf + 10.0f, 20.0f);

        if (gx >= 0 && gx < NX_ && gy >= 0 && gy < NY_ && gz >= 0 && gz < 1) {
            int flat = ((b /*NZ=1*/ + gz) * NY_ + gy) * NX_ + gx;
            const float4 xv = *(const float4*)(xb + (size_t)n * (D_ * H_ * W_ * C_));
            if (flat == cur) {
                acc.x += xv.x; acc.y += xv.y; acc.z += xv.z; acc.w += xv.w;
            } else {
                if (cur >= 0)
                    red_add_v4(g_scratch + (size_t)cur * C_ + sub * 4, acc);
                cur = flat; acc = xv;
            }
        }
    }
    if (cur >= 0)
        red_add_v4(g_scratch + (size_t)cur * C_ + sub * 4, acc);
}

// ---------------------------------------------------------------------------
// Transpose scratch (B,NY,NX,C) -> out (B, C, NY, NX). Tiled via SMEM:
// coalesced float4 reads, per-warp coalesced 128B writes per channel plane.
// ---------------------------------------------------------------------------
__global__ void transpose_kernel(float* __restrict__ out) {
    __shared__ float s[32][C_ + 1];
    int tile = blockIdx.x;                    // B * NY * (NX/32) = 2304
    int xt = tile % (NX_ / 32);
    int y  = (tile / (NX_ / 32)) % NY_;
    int b  = tile / ((NX_ / 32) * NY_);

    const float4* src = (const float4*)(g_scratch
        + (((size_t)b * NY_ + y) * NX_ + (size_t)xt * 32) * C_);

    int t = threadIdx.x;                      // 256 threads
    for (int i = t; i < 32 * C_ / 4; i += 256) {
        float4 val = src[i];
        int xx = i >> 4;                      // / (C_/4)
        int cc = (i & 15) << 2;
        s[xx][cc + 0] = val.x; s[xx][cc + 1] = val.y;
        s[xx][cc + 2] = val.z; s[xx][cc + 3] = val.w;
    }
    __syncthreads();

    int lanex = t & 31;
    int cw = t >> 5;                          // warp id 0..7
    size_t obase = (((size_t)b * C_) * NY_ + y) * NX_ + (size_t)xt * 32 + lanex;
    for (int c = cw; c < C_; c += 8) {
        out[obase + (size_t)c * (NY_ * NX_)] = s[lanex][c];
    }
}

// ---------------------------------------------------------------------------
extern "C" void kernel_launch(void* const* d_in, const int* in_sizes, int n_in,
                              void* d_out, int out_size) {
    // Resolve inputs by element count (robust to metadata ordering):
    //   x: B*N*D*H*W*C = 41,287,680   pose: B*N*16 = 128   intrinsics: B*N*9 = 72
    const float* x    = nullptr;
    const float* intr = nullptr;
    const float* pose = nullptr;
    for (int i = 0; i < n_in; i++) {
        if (in_sizes[i] == B_ * N_ * 16)      pose = (const float*)d_in[i];
        else if (in_sizes[i] == B_ * N_ * 9)  intr = (const float*)d_in[i];
        else                                  x    = (const float*)d_in[i];
    }
    float* out = (float*)d_out;

    setup_kernel<<<1, 32>>>(intr, pose);
    zero_kernel<<<1184, 256>>>();             // grid-stride, ~8 blocks/SM

    const int ngroups  = B_ * D_ * H_ * W_;      // 322,560 half-warp groups
    const int nthreads = ngroups * 16;           // 16 lanes per group
    scatter_kernel<<<(nthreads + 255) / 256, 256>>>(x);

    transpose_kernel<<<B_ * NY_ * (NX_ / 32), 256>>>(out);
}